// round 12
// baseline (speedup 1.0000x reference)
#include <cuda_runtime.h>
#include <cuda_bf16.h>
#include <math.h>
#include <stdint.h>

// Problem constants: N=64, T=512, D=512, H=512, fp32
#define NB   64
#define TT   512
#define DD   512
#define HH   512
#define MM   (NB * TT)

// ---------------------------------------------------------------------------
// f32x2 packed-math helpers
// ---------------------------------------------------------------------------
__device__ __forceinline__ void ffma2(unsigned long long& acc,
                                      unsigned long long a,
                                      unsigned long long b) {
    asm("fma.rn.f32x2 %0, %1, %2, %0;" : "+l"(acc) : "l"(a), "l"(b));
}
__device__ __forceinline__ unsigned long long add2(unsigned long long a,
                                                   unsigned long long b) {
    unsigned long long r;
    asm("add.rn.f32x2 %0, %1, %2;" : "=l"(r) : "l"(a), "l"(b));
    return r;
}
__device__ __forceinline__ unsigned long long pack_dup(float v) {
    unsigned long long r;
    unsigned u = __float_as_uint(v);
    asm("mov.b64 %0, {%1, %1};" : "=l"(r) : "r"(u));
    return r;
}
__device__ __forceinline__ unsigned long long pack2(float lo, float hi) {
    unsigned long long r;
    asm("mov.b64 %0, {%1, %2};" : "=l"(r) : "f"(lo), "f"(hi));
    return r;
}

// mbarrier helpers -----------------------------------------------------------
#define MBAR_INIT(addr, cnt) \
    asm volatile("mbarrier.init.shared.b64 [%0], %1;" :: "r"(addr), "r"(cnt) : "memory")
#define MBAR_EXPECT_TX(addr, bytes) \
    asm volatile("mbarrier.arrive.expect_tx.shared.b64 _, [%0], %1;" \
                 :: "r"(addr), "r"(bytes) : "memory")

__device__ __forceinline__ void mbar_wait_parity(uint32_t mbar, uint32_t parity) {
    asm volatile(
        "{\n\t"
        ".reg .pred P;\n\t"
        "WL_%=:\n\t"
        "mbarrier.try_wait.parity.acquire.cluster.shared::cta.b64 P, [%0], %1, 0x989680;\n\t"
        "@P bra WD_%=;\n\t"
        "bra WL_%=;\n\t"
        "WD_%=:\n\t"
        "}" :: "r"(mbar), "r"(parity) : "memory");
}

__device__ __forceinline__ void st_async_b64(uint32_t raddr, unsigned long long v,
                                             uint32_t rmbar) {
    asm volatile(
        "st.async.shared::cluster.mbarrier::complete_tx::bytes.b64 [%0], %1, [%2];"
        :: "r"(raddr), "l"(v), "r"(rmbar) : "memory");
}

__device__ __forceinline__ unsigned long long shfl_down16_b64(unsigned long long v) {
    unsigned lo = (unsigned)(v & 0xFFFFFFFFULL);
    unsigned hi = (unsigned)(v >> 32);
    lo = __shfl_down_sync(0xFFFFFFFFu, lo, 16);
    hi = __shfl_down_sync(0xFFFFFFFFu, hi, 16);
    return ((unsigned long long)hi << 32) | lo;
}

// ---------------------------------------------------------------------------
// Kernel A: xwx = x @ Wx + b  (into d_out), FFMA2 SGEMM (unchanged)
// ---------------------------------------------------------------------------
#define BM 128
#define BN 128
#define BK 8

__global__ __launch_bounds__(256) void gemm_xwx_kernel(
    const float* __restrict__ X,
    const float* __restrict__ Wx,
    const float* __restrict__ bias,
    float* __restrict__ out)
{
    __shared__ float2 Asd[BK][BM];
    __shared__ float  Bs[BK][BN];

    const int tid = threadIdx.x;
    const int m0 = blockIdx.y * BM;
    const int n0 = blockIdx.x * BN;

    const int arow = tid >> 1;
    const int acol = (tid & 1) * 4;
    const int brow = tid >> 5;
    const int bcol = (tid & 31) * 4;

    const int ty = tid >> 4;
    const int tx = tid & 15;

    unsigned long long acc2[8][4];
#pragma unroll
    for (int i = 0; i < 8; ++i)
#pragma unroll
        for (int j = 0; j < 4; ++j) acc2[i][j] = 0ULL;

    for (int k0 = 0; k0 < DD; k0 += BK) {
        float4 av = *reinterpret_cast<const float4*>(
            X + (size_t)(m0 + arow) * DD + k0 + acol);
        float4 bv = *reinterpret_cast<const float4*>(
            Wx + (size_t)(k0 + brow) * HH + n0 + bcol);

        Asd[acol + 0][arow] = make_float2(av.x, av.x);
        Asd[acol + 1][arow] = make_float2(av.y, av.y);
        Asd[acol + 2][arow] = make_float2(av.z, av.z);
        Asd[acol + 3][arow] = make_float2(av.w, av.w);
        *reinterpret_cast<float4*>(&Bs[brow][bcol]) = bv;
        __syncthreads();

#pragma unroll
        for (int k = 0; k < BK; ++k) {
            unsigned long long a2[8], b2[4];
            ulonglong2 t0 = *reinterpret_cast<const ulonglong2*>(&Bs[k][tx * 8]);
            ulonglong2 t1 = *reinterpret_cast<const ulonglong2*>(&Bs[k][tx * 8 + 4]);
            b2[0] = t0.x; b2[1] = t0.y; b2[2] = t1.x; b2[3] = t1.y;
#pragma unroll
            for (int i = 0; i < 8; ++i)
                a2[i] = *reinterpret_cast<const unsigned long long*>(&Asd[k][ty * 8 + i]);
#pragma unroll
            for (int i = 0; i < 8; ++i)
#pragma unroll
                for (int j = 0; j < 4; ++j)
                    ffma2(acc2[i][j], a2[i], b2[j]);
        }
        __syncthreads();
    }

    unsigned long long bb2[4];
    {
        ulonglong2 t0 = *reinterpret_cast<const ulonglong2*>(bias + n0 + tx * 8);
        ulonglong2 t1 = *reinterpret_cast<const ulonglong2*>(bias + n0 + tx * 8 + 4);
        bb2[0] = t0.x; bb2[1] = t0.y; bb2[2] = t1.x; bb2[3] = t1.y;
    }
#pragma unroll
    for (int i = 0; i < 8; ++i) {
        float* orow = out + (size_t)(m0 + ty * 8 + i) * HH + n0 + tx * 8;
        ulonglong2 v0, v1;
        v0.x = add2(acc2[i][0], bb2[0]);
        v0.y = add2(acc2[i][1], bb2[1]);
        v1.x = add2(acc2[i][2], bb2[2]);
        v1.y = add2(acc2[i][3], bb2[3]);
        *reinterpret_cast<ulonglong2*>(orow)     = v0;
        *reinterpret_cast<ulonglong2*>(orow + 4) = v1;
    }
}

// ---------------------------------------------------------------------------
// Kernel B: cluster recurrence, TWO pipelined batch groups per cluster.
//   8 clusters x 8 CTAs; cluster owns 8 batch rows = 2 groups of 4.
//   Wh register slice SHARED by both groups. Per step:
//     waitA -> kloopA -> STS_A -> waitB (arrived during kloopA) -> kloopB
//     (reusing A's acc regs) -> one bar -> warps 0-7 reduce/store group A
//     while warps 8-15 do group B in parallel.
//   Protocol per group = R10 wait-free design (32 full barriers, pre-armed
//   both phases; elected re-arm right after wait; no empty barriers — the
//   anti-dependency is implied by the full-barrier causal chain).
// ---------------------------------------------------------------------------
#define CLUSTER       8
#define NCTA          64            // 8 clusters x 8
#define NGROUPS       2
#define BATCH_PER_G   4
#define COLS_PER_CTA  64

#define HBUF_G_ELEMS  (2 * BATCH_PER_G * HH)            // 4096 floats / group
#define RED16_ELEMS   (16 * BATCH_PER_G * COLS_PER_CTA) // 4096 floats / buf
#define RED_G_ELEMS   (2 * RED16_ELEMS)                 // 8192 floats / group
#define HBUF_TOT      (NGROUPS * HBUF_G_ELEMS)          // 8192 floats (32 KB)
#define RED_TOT       (NGROUPS * RED_G_ELEMS)           // 16384 floats (64 KB)
#define MBAR_OFF      ((HBUF_TOT + RED_TOT) * 4)        // 98304 bytes
// mbar: full[g][p][r] at MBAR_OFF + (g*16 + p*8 + r)*8  -> 256 bytes
#define MB_FULL(g, p, r) (MBAR_OFF + (((g) * 16) + ((p) * 8) + (r)) * 8)
#define RNN_SMEM_BYTES (MBAR_OFF + 256)

#define CHUNK_TX_BYTES 1024   // 128 producer threads x 8 B per peer chunk

__global__ __launch_bounds__(512, 1) __cluster_dims__(CLUSTER, 1, 1)
void rnn_cluster_kernel(const float* __restrict__ h0,
                        const float* __restrict__ Wh,
                        float* __restrict__ out)
{
    extern __shared__ float smem[];
    float* hbuf = smem;                 // [g][buf][4][HH]
    float* red  = smem + HBUF_TOT;      // [g][buf][16][4][64]

    const int tid = threadIdx.x;
    uint32_t rank;
    asm("mov.u32 %0, %%cluster_ctarank;" : "=r"(rank));
    const int cid = blockIdx.x >> 3;
    const int b0  = cid * (NGROUPS * BATCH_PER_G);   // 8 rows per cluster

    const int kq    = tid >> 4;          // 0..31
    const int cq    = tid & 15;          // 0..15
    const int kbase = kq * 16;
    const int kq2   = tid >> 5;          // warp id 0..15
    const int chunk = tid >> 6;          // 0..7: source rank my warp consumes
    const int jg0   = (int)rank * COLS_PER_CTA + cq * 4;

    // ---- Wh slice -> registers (once; shared by both groups) ----
    unsigned long long w01[16], w23[16];
#pragma unroll
    for (int kk = 0; kk < 16; ++kk) {
        ulonglong2 v = *reinterpret_cast<const ulonglong2*>(
            Wh + (size_t)(kbase + kk) * HH + jg0);
        w01[kk] = v.x;
        w23[kk] = v.y;
    }

    uint32_t smem_u32;
    asm("{ .reg .u64 t; cvta.to.shared.u64 t, %1; cvt.u32.u64 %0, t; }"
        : "=r"(smem_u32) : "l"(smem));

    // ---- init: mbarriers + h0 into buffer 0 of both groups ----
    if (tid == 0) {
#pragma unroll
        for (int g = 0; g < NGROUPS; ++g)
#pragma unroll
            for (int r = 0; r < CLUSTER; ++r) {
                MBAR_INIT(smem_u32 + MB_FULL(g, 0, r), 1);
                MBAR_INIT(smem_u32 + MB_FULL(g, 1, r), 1);
                MBAR_EXPECT_TX(smem_u32 + MB_FULL(g, 0, r), CHUNK_TX_BYTES);
                MBAR_EXPECT_TX(smem_u32 + MB_FULL(g, 1, r), CHUNK_TX_BYTES);
            }
    }
    // h0 rows: group g buf0 at hbuf[g*4096 + 0 + b*HH + k]
    for (int idx = tid; idx < NGROUPS * BATCH_PER_G * HH; idx += 512) {
        int g = idx / (BATCH_PER_G * HH);
        int rkk = idx - g * (BATCH_PER_G * HH);
        hbuf[g * HBUF_G_ELEMS + rkk] = h0[(size_t)b0 * HH + idx];
    }
    __syncthreads();
    asm volatile("barrier.cluster.arrive.aligned;\n\t"
                 "barrier.cluster.wait.aligned;" ::: "memory");

    // peer smem base addresses (mapa once)
    uint32_t rbase[CLUSTER];
#pragma unroll
    for (int p = 0; p < CLUSTER; ++p)
        asm("mapa.shared::cluster.u32 %0, %1, %2;"
            : "=r"(rbase[p]) : "r"(smem_u32), "r"(p));

    // reduce/store mapping: tid<256 -> group 0; tid>=256 -> group 1
    const int gm  = tid >> 8;            // my reduce group
    const int rt  = tid & 255;
    const int fb  = (rt >> 6) & 3;
    const int fc  = rt & 63;
    const int jg  = (int)rank * COLS_PER_CTA + fc;
    float* outp = out + ((size_t)(b0 + gm * BATCH_PER_G + fb) * TT) * HH + jg;
    const bool is_store = ((tid & 1) == 0);
    const bool is_arm   = ((tid & 63) == 0);   // one re-armer per chunk

    int pf0[2] = {0, 0};   // parity for full[0][buf][chunk]
    int pf1[2] = {0, 0};   // parity for full[1][buf][chunk]

    for (int t = 0; t < TT; ++t) {
        const int p = t & 1;
        const int q = p ^ 1;

        // prefetch xwx for this step (every thread reduces one output now)
        float xw = outp[(size_t)t * HH];

        // ================= group 0: wait + kloop + STS =================
        if (t > 0) {
            mbar_wait_parity(smem_u32 + MB_FULL(0, p, chunk), (uint32_t)pf0[p]);
            pf0[p] ^= 1;
            if (is_arm)
                MBAR_EXPECT_TX(smem_u32 + MB_FULL(0, p, chunk), CHUNK_TX_BYTES);
        }
        {
            const float* hc = hbuf + 0 * HBUF_G_ELEMS + p * (BATCH_PER_G * HH);
            unsigned long long a01[4] = {0ULL, 0ULL, 0ULL, 0ULL};
            unsigned long long a23[4] = {0ULL, 0ULL, 0ULL, 0ULL};
#pragma unroll
            for (int kk4 = 0; kk4 < 4; ++kk4) {
                const int k = kbase + kk4 * 4;
#pragma unroll
                for (int b = 0; b < 4; ++b) {
                    float4 hv = *reinterpret_cast<const float4*>(&hc[b * HH + k]);
                    unsigned long long hh;
                    hh = pack_dup(hv.x);
                    ffma2(a01[b], hh, w01[kk4 * 4 + 0]);
                    ffma2(a23[b], hh, w23[kk4 * 4 + 0]);
                    hh = pack_dup(hv.y);
                    ffma2(a01[b], hh, w01[kk4 * 4 + 1]);
                    ffma2(a23[b], hh, w23[kk4 * 4 + 1]);
                    hh = pack_dup(hv.z);
                    ffma2(a01[b], hh, w01[kk4 * 4 + 2]);
                    ffma2(a23[b], hh, w23[kk4 * 4 + 2]);
                    hh = pack_dup(hv.w);
                    ffma2(a01[b], hh, w01[kk4 * 4 + 3]);
                    ffma2(a23[b], hh, w23[kk4 * 4 + 3]);
                }
            }
#pragma unroll
            for (int b = 0; b < 4; ++b) {
                a01[b] = add2(a01[b], shfl_down16_b64(a01[b]));
                a23[b] = add2(a23[b], shfl_down16_b64(a23[b]));
            }
            float* rp = red + 0 * RED_G_ELEMS + p * RED16_ELEMS;
            if ((tid & 16) == 0) {
#pragma unroll
                for (int b = 0; b < 4; ++b) {
                    ulonglong2 v;
                    v.x = a01[b];
                    v.y = a23[b];
                    *reinterpret_cast<ulonglong2*>(
                        &rp[(kq2 * BATCH_PER_G + b) * COLS_PER_CTA + cq * 4]) = v;
                }
            }
        }

        // ================= group 1: wait + kloop + STS =================
        if (t > 0) {
            mbar_wait_parity(smem_u32 + MB_FULL(1, p, chunk), (uint32_t)pf1[p]);
            pf1[p] ^= 1;
            if (is_arm)
                MBAR_EXPECT_TX(smem_u32 + MB_FULL(1, p, chunk), CHUNK_TX_BYTES);
        }
        {
            const float* hc = hbuf + 1 * HBUF_G_ELEMS + p * (BATCH_PER_G * HH);
            unsigned long long a01[4] = {0ULL, 0ULL, 0ULL, 0ULL};
            unsigned long long a23[4] = {0ULL, 0ULL, 0ULL, 0ULL};
#pragma unroll
            for (int kk4 = 0; kk4 < 4; ++kk4) {
                const int k = kbase + kk4 * 4;
#pragma unroll
                for (int b = 0; b < 4; ++b) {
                    float4 hv = *reinterpret_cast<const float4*>(&hc[b * HH + k]);
                    unsigned long long hh;
                    hh = pack_dup(hv.x);
                    ffma2(a01[b], hh, w01[kk4 * 4 + 0]);
                    ffma2(a23[b], hh, w23[kk4 * 4 + 0]);
                    hh = pack_dup(hv.y);
                    ffma2(a01[b], hh, w01[kk4 * 4 + 1]);
                    ffma2(a23[b], hh, w23[kk4 * 4 + 1]);
                    hh = pack_dup(hv.z);
                    ffma2(a01[b], hh, w01[kk4 * 4 + 2]);
                    ffma2(a23[b], hh, w23[kk4 * 4 + 2]);
                    hh = pack_dup(hv.w);
                    ffma2(a01[b], hh, w01[kk4 * 4 + 3]);
                    ffma2(a23[b], hh, w23[kk4 * 4 + 3]);
                }
            }
#pragma unroll
            for (int b = 0; b < 4; ++b) {
                a01[b] = add2(a01[b], shfl_down16_b64(a01[b]));
                a23[b] = add2(a23[b], shfl_down16_b64(a23[b]));
            }
            float* rp = red + 1 * RED_G_ELEMS + p * RED16_ELEMS;
            if ((tid & 16) == 0) {
#pragma unroll
                for (int b = 0; b < 4; ++b) {
                    ulonglong2 v;
                    v.x = a01[b];
                    v.y = a23[b];
                    *reinterpret_cast<ulonglong2*>(
                        &rp[(kq2 * BATCH_PER_G + b) * COLS_PER_CTA + cq * 4]) = v;
                }
            }
        }

        __syncthreads();   // the ONLY block barrier per step

        // ============ parallel tails: warps 0-7 -> A, 8-15 -> B ============
        {
            const float* rp = red + gm * RED_G_ELEMS + p * RED16_ELEMS;
            float s0 = xw, s1 = 0.f, s2 = 0.f, s3 = 0.f;
#pragma unroll
            for (int qd = 0; qd < 4; ++qd) {
                s0 += rp[((4 * qd + 0) * BATCH_PER_G + fb) * COLS_PER_CTA + fc];
                s1 += rp[((4 * qd + 1) * BATCH_PER_G + fb) * COLS_PER_CTA + fc];
                s2 += rp[((4 * qd + 2) * BATCH_PER_G + fb) * COLS_PER_CTA + fc];
                s3 += rp[((4 * qd + 3) * BATCH_PER_G + fb) * COLS_PER_CTA + fc];
            }
            float s = (s0 + s1) + (s2 + s3);
            float r;
            asm("tanh.approx.f32 %0, %1;" : "=f"(r) : "f"(s));
            outp[(size_t)t * HH] = r;

            if (t + 1 < TT) {
                // WAIT-FREE store (R10 causal chain, per group).
                float rn = __shfl_down_sync(0xFFFFFFFFu, r, 1);
                if (is_store) {
                    unsigned long long v = pack2(r, rn);
                    const uint32_t off =
                        (uint32_t)((gm * HBUF_G_ELEMS) +
                                   (q * BATCH_PER_G + fb) * HH + jg) * 4u;
                    const uint32_t mboff = (uint32_t)MB_FULL(gm, q, (int)rank);
#pragma unroll
                    for (int pp = 0; pp < CLUSTER; ++pp)
                        st_async_b64(rbase[pp] + off, v, rbase[pp] + mboff);
                }
            }
        }
        // no trailing barrier: red double-buffered per group; cross-step
        // ordering guaranteed by bar(t) between reduce-read(t-1) and STS(t+1).
    }

    // drain before exit
    asm volatile("barrier.cluster.arrive.aligned;\n\t"
                 "barrier.cluster.wait.aligned;" ::: "memory");
}

// ---------------------------------------------------------------------------
// Launch
// ---------------------------------------------------------------------------
extern "C" void kernel_launch(void* const* d_in, const int* in_sizes, int n_in,
                              void* d_out, int out_size) {
    const float* x  = (const float*)d_in[0];
    const float* h0 = (const float*)d_in[1];
    const float* Wx = (const float*)d_in[2];
    const float* Wh = (const float*)d_in[3];
    const float* b  = (const float*)d_in[4];
    float* out = (float*)d_out;

    (void)in_sizes; (void)n_in; (void)out_size;

    dim3 gridA(HH / BN, MM / BM);
    gemm_xwx_kernel<<<gridA, 256>>>(x, Wx, b, out);

    cudaFuncSetAttribute(rnn_cluster_kernel,
                         cudaFuncAttributeMaxDynamicSharedMemorySize,
                         RNN_SMEM_BYTES);
    rnn_cluster_kernel<<<NCTA, 512, RNN_SMEM_BYTES>>>(h0, Wh, out);
}

// round 13
// speedup vs baseline: 1.0384x; 1.0384x over previous
#include <cuda_runtime.h>
#include <cuda_bf16.h>
#include <math.h>
#include <stdint.h>

// Problem constants: N=64, T=512, D=512, H=512, fp32
#define NB   64
#define TT   512
#define DD   512
#define HH   512
#define MM   (NB * TT)

// ---------------------------------------------------------------------------
// f32x2 packed-math helpers
// ---------------------------------------------------------------------------
__device__ __forceinline__ void ffma2(unsigned long long& acc,
                                      unsigned long long a,
                                      unsigned long long b) {
    asm("fma.rn.f32x2 %0, %1, %2, %0;" : "+l"(acc) : "l"(a), "l"(b));
}
__device__ __forceinline__ unsigned long long add2(unsigned long long a,
                                                   unsigned long long b) {
    unsigned long long r;
    asm("add.rn.f32x2 %0, %1, %2;" : "=l"(r) : "l"(a), "l"(b));
    return r;
}
__device__ __forceinline__ unsigned long long pack_dup(float v) {
    unsigned long long r;
    unsigned u = __float_as_uint(v);
    asm("mov.b64 %0, {%1, %1};" : "=l"(r) : "r"(u));
    return r;
}
__device__ __forceinline__ unsigned long long pack2(float lo, float hi) {
    unsigned long long r;
    asm("mov.b64 %0, {%1, %2};" : "=l"(r) : "f"(lo), "f"(hi));
    return r;
}

// mbarrier helpers -----------------------------------------------------------
#define MBAR_INIT(addr, cnt) \
    asm volatile("mbarrier.init.shared.b64 [%0], %1;" :: "r"(addr), "r"(cnt) : "memory")
#define MBAR_EXPECT_TX(addr, bytes) \
    asm volatile("mbarrier.arrive.expect_tx.shared.b64 _, [%0], %1;" \
                 :: "r"(addr), "r"(bytes) : "memory")

__device__ __forceinline__ void mbar_wait_parity(uint32_t mbar, uint32_t parity) {
    asm volatile(
        "{\n\t"
        ".reg .pred P;\n\t"
        "WL_%=:\n\t"
        "mbarrier.try_wait.parity.acquire.cluster.shared::cta.b64 P, [%0], %1, 0x989680;\n\t"
        "@P bra WD_%=;\n\t"
        "bra WL_%=;\n\t"
        "WD_%=:\n\t"
        "}" :: "r"(mbar), "r"(parity) : "memory");
}

__device__ __forceinline__ void st_async_b64(uint32_t raddr, unsigned long long v,
                                             uint32_t rmbar) {
    asm volatile(
        "st.async.shared::cluster.mbarrier::complete_tx::bytes.b64 [%0], %1, [%2];"
        :: "r"(raddr), "l"(v), "r"(rmbar) : "memory");
}

__device__ __forceinline__ unsigned long long shfl_down16_b64(unsigned long long v) {
    unsigned lo = (unsigned)(v & 0xFFFFFFFFULL);
    unsigned hi = (unsigned)(v >> 32);
    lo = __shfl_down_sync(0xFFFFFFFFu, lo, 16);
    hi = __shfl_down_sync(0xFFFFFFFFu, hi, 16);
    return ((unsigned long long)hi << 32) | lo;
}

// ---------------------------------------------------------------------------
// Kernel A: xwx = x @ Wx + b  (into d_out), FFMA2 SGEMM.
//   NEW vs R11: BK=16, double-buffered SMEM + register prefetch (LDG next
//   tile during compute, STS to alternate buffer, ONE bar per iter),
//   __launch_bounds__(256,2) -> 2 CTAs/SM (4 warps/SMSP) for latency hiding.
// ---------------------------------------------------------------------------
#define BM 128
#define BN 128
#define BK 16
#define KITERS (DD / BK)   // 32

__global__ __launch_bounds__(256, 2) void gemm_xwx_kernel(
    const float* __restrict__ X,
    const float* __restrict__ Wx,
    const float* __restrict__ bias,
    float* __restrict__ out)
{
    __shared__ float2 Asd[2][BK][BM];   // duplicated A: {a,a}; 2 buffers, 32 KB
    __shared__ float  Bs[2][BK][BN];    // 2 buffers, 16 KB

    const int tid = threadIdx.x;
    const int m0 = blockIdx.y * BM;
    const int n0 = blockIdx.x * BN;

    // A tile: 128x16 floats; thread -> row (tid>>1), k-offset (tid&1)*8
    const int arow = tid >> 1;
    const int acol = (tid & 1) * 8;
    // B tile: 16x128 floats; thread -> k-row (tid>>4), col (tid&15)*8
    const int brow = tid >> 4;
    const int bcol = (tid & 15) * 8;

    const int ty = tid >> 4;
    const int tx = tid & 15;

    const float* aptr = X + (size_t)(m0 + arow) * DD + acol;
    const float* bptr = Wx + (size_t)brow * HH + n0 + bcol;

    unsigned long long acc2[8][4];
#pragma unroll
    for (int i = 0; i < 8; ++i)
#pragma unroll
        for (int j = 0; j < 4; ++j) acc2[i][j] = 0ULL;

    // preload tile 0 into buffer 0
    float4 av0 = *reinterpret_cast<const float4*>(aptr);
    float4 av1 = *reinterpret_cast<const float4*>(aptr + 4);
    float4 bv0 = *reinterpret_cast<const float4*>(bptr);
    float4 bv1 = *reinterpret_cast<const float4*>(bptr + 4);
    {
        Asd[0][acol + 0][arow] = make_float2(av0.x, av0.x);
        Asd[0][acol + 1][arow] = make_float2(av0.y, av0.y);
        Asd[0][acol + 2][arow] = make_float2(av0.z, av0.z);
        Asd[0][acol + 3][arow] = make_float2(av0.w, av0.w);
        Asd[0][acol + 4][arow] = make_float2(av1.x, av1.x);
        Asd[0][acol + 5][arow] = make_float2(av1.y, av1.y);
        Asd[0][acol + 6][arow] = make_float2(av1.z, av1.z);
        Asd[0][acol + 7][arow] = make_float2(av1.w, av1.w);
        *reinterpret_cast<float4*>(&Bs[0][brow][bcol])     = bv0;
        *reinterpret_cast<float4*>(&Bs[0][brow][bcol + 4]) = bv1;
    }
    __syncthreads();

    for (int it = 0; it < KITERS; ++it) {
        const int cur = it & 1;
        const int nxt = cur ^ 1;

        // prefetch next tile into registers (latency hides under compute)
        if (it + 1 < KITERS) {
            const float* ap = aptr + (it + 1) * BK;
            const float* bp = bptr + (size_t)(it + 1) * BK * HH;
            av0 = *reinterpret_cast<const float4*>(ap);
            av1 = *reinterpret_cast<const float4*>(ap + 4);
            bv0 = *reinterpret_cast<const float4*>(bp);
            bv1 = *reinterpret_cast<const float4*>(bp + 4);
        }

#pragma unroll
        for (int k = 0; k < BK; ++k) {
            unsigned long long a2[8], b2[4];
            ulonglong2 t0 = *reinterpret_cast<const ulonglong2*>(&Bs[cur][k][tx * 8]);
            ulonglong2 t1 = *reinterpret_cast<const ulonglong2*>(&Bs[cur][k][tx * 8 + 4]);
            b2[0] = t0.x; b2[1] = t0.y; b2[2] = t1.x; b2[3] = t1.y;
#pragma unroll
            for (int i = 0; i < 8; ++i)
                a2[i] = *reinterpret_cast<const unsigned long long*>(&Asd[cur][k][ty * 8 + i]);
#pragma unroll
            for (int i = 0; i < 8; ++i)
#pragma unroll
                for (int j = 0; j < 4; ++j)
                    ffma2(acc2[i][j], a2[i], b2[j]);
        }

        // stage next tile into the other buffer
        if (it + 1 < KITERS) {
            Asd[nxt][acol + 0][arow] = make_float2(av0.x, av0.x);
            Asd[nxt][acol + 1][arow] = make_float2(av0.y, av0.y);
            Asd[nxt][acol + 2][arow] = make_float2(av0.z, av0.z);
            Asd[nxt][acol + 3][arow] = make_float2(av0.w, av0.w);
            Asd[nxt][acol + 4][arow] = make_float2(av1.x, av1.x);
            Asd[nxt][acol + 5][arow] = make_float2(av1.y, av1.y);
            Asd[nxt][acol + 6][arow] = make_float2(av1.z, av1.z);
            Asd[nxt][acol + 7][arow] = make_float2(av1.w, av1.w);
            *reinterpret_cast<float4*>(&Bs[nxt][brow][bcol])     = bv0;
            *reinterpret_cast<float4*>(&Bs[nxt][brow][bcol + 4]) = bv1;
        }
        __syncthreads();   // one barrier per iter
    }

    unsigned long long bb2[4];
    {
        ulonglong2 t0 = *reinterpret_cast<const ulonglong2*>(bias + n0 + tx * 8);
        ulonglong2 t1 = *reinterpret_cast<const ulonglong2*>(bias + n0 + tx * 8 + 4);
        bb2[0] = t0.x; bb2[1] = t0.y; bb2[2] = t1.x; bb2[3] = t1.y;
    }
#pragma unroll
    for (int i = 0; i < 8; ++i) {
        float* orow = out + (size_t)(m0 + ty * 8 + i) * HH + n0 + tx * 8;
        ulonglong2 v0, v1;
        v0.x = add2(acc2[i][0], bb2[0]);
        v0.y = add2(acc2[i][1], bb2[1]);
        v1.x = add2(acc2[i][2], bb2[2]);
        v1.y = add2(acc2[i][3], bb2[3]);
        *reinterpret_cast<ulonglong2*>(orow)     = v0;
        *reinterpret_cast<ulonglong2*>(orow + 4) = v1;
    }
}

// ---------------------------------------------------------------------------
// Kernel B: cluster recurrence — EXACT R10 version (best measured: 1178 us).
// Chunked full barriers, wait-free producer stores (empty barriers proven
// redundant via the full-barrier causal chain), elected re-arm after wait,
// shfl pre-reduce, double-buffered red, one block barrier per step.
// ---------------------------------------------------------------------------
#define CLUSTER       8
#define NCTA          128
#define BATCH_PER_CL  4
#define COLS_PER_CTA  64

#define HBUF_ELEMS  (2 * BATCH_PER_CL * HH)              // 4096 floats (16 KB)
#define RED16_ELEMS (16 * BATCH_PER_CL * COLS_PER_CTA)   // 4096 floats (16 KB)
#define MBAR_OFF    ((HBUF_ELEMS + 2 * RED16_ELEMS) * 4) // 49152 bytes
#define MB_FULL(p, r) (MBAR_OFF + ((p) * 8 + (r)) * 8)
#define RNN_SMEM_BYTES (MBAR_OFF + 128)

#define CHUNK_TX_BYTES 1024   // 128 producer threads x 8 B land per peer chunk

__global__ __launch_bounds__(512, 1) __cluster_dims__(CLUSTER, 1, 1)
void rnn_cluster_kernel(const float* __restrict__ h0,
                        const float* __restrict__ Wh,
                        float* __restrict__ out)
{
    extern __shared__ float smem[];
    float* hbuf = smem;                       // [2][4][HH]
    float* red  = smem + HBUF_ELEMS;          // [2][16][4][64]

    const int tid = threadIdx.x;
    uint32_t rank;
    asm("mov.u32 %0, %%cluster_ctarank;" : "=r"(rank));
    const int cid = blockIdx.x >> 3;
    const int b0  = cid * BATCH_PER_CL;

    const int kq    = tid >> 4;          // 0..31
    const int cq    = tid & 15;          // 0..15
    const int kbase = kq * 16;
    const int kq2   = tid >> 5;          // warp id 0..15
    const int chunk = tid >> 6;          // 0..7: source rank my warp consumes
    const int jg0   = (int)rank * COLS_PER_CTA + cq * 4;

    // ---- Wh slice -> registers (once) ----
    unsigned long long w01[16], w23[16];
#pragma unroll
    for (int kk = 0; kk < 16; ++kk) {
        ulonglong2 v = *reinterpret_cast<const ulonglong2*>(
            Wh + (size_t)(kbase + kk) * HH + jg0);
        w01[kk] = v.x;
        w23[kk] = v.y;
    }

    uint32_t smem_u32;
    asm("{ .reg .u64 t; cvta.to.shared.u64 t, %1; cvt.u32.u64 %0, t; }"
        : "=r"(smem_u32) : "l"(smem));

    // ---- init: mbarriers + h0 into buffer 0 ----
    if (tid == 0) {
#pragma unroll
        for (int r = 0; r < CLUSTER; ++r) {
            MBAR_INIT(smem_u32 + MB_FULL(0, r), 1);
            MBAR_INIT(smem_u32 + MB_FULL(1, r), 1);
            MBAR_EXPECT_TX(smem_u32 + MB_FULL(0, r), CHUNK_TX_BYTES);
            MBAR_EXPECT_TX(smem_u32 + MB_FULL(1, r), CHUNK_TX_BYTES);
        }
    }
    for (int idx = tid; idx < BATCH_PER_CL * HH; idx += 512)
        hbuf[idx] = h0[(size_t)b0 * HH + idx];
    __syncthreads();
    asm volatile("barrier.cluster.arrive.aligned;\n\t"
                 "barrier.cluster.wait.aligned;" ::: "memory");

    // peer smem base addresses (mapa once)
    uint32_t rbase[CLUSTER];
#pragma unroll
    for (int p = 0; p < CLUSTER; ++p)
        asm("mapa.shared::cluster.u32 %0, %1, %2;"
            : "=r"(rbase[p]) : "r"(smem_u32), "r"(p));

    // output-stage mapping (threads < 256)
    const int fb = (tid >> 6) & 3;
    const int fc = tid & 63;
    const int jg = (int)rank * COLS_PER_CTA + fc;
    float* outp = out + ((size_t)(b0 + fb) * TT) * HH + jg;
    const bool is_red   = (tid < 256);
    const bool is_store = (tid < 256) && ((tid & 1) == 0);
    const bool is_arm   = ((tid & 63) == 0);   // one re-armer per chunk
    const bool is_lo    = ((tid & 16) == 0);   // lane < 16 within warp

    int pf[2] = {0, 0};   // per-warp parity for full[buf][chunk]

#pragma unroll 2
    for (int t = 0; t < TT; ++t) {
        const int p = t & 1;
        const int q = p ^ 1;

        // prefetch xwx for this step (independent of h)
        float xw = 0.0f;
        if (is_red) xw = outp[(size_t)t * HH];

        // wait only for MY chunk of h_t; elected thread re-arms immediately.
        if (t > 0) {
            mbar_wait_parity(smem_u32 + MB_FULL(p, chunk), (uint32_t)pf[p]);
            pf[p] ^= 1;
            if (is_arm)
                MBAR_EXPECT_TX(smem_u32 + MB_FULL(p, chunk), CHUNK_TX_BYTES);
        }

        const float* hc = hbuf + p * (BATCH_PER_CL * HH);
        unsigned long long a01[4] = {0ULL, 0ULL, 0ULL, 0ULL};
        unsigned long long a23[4] = {0ULL, 0ULL, 0ULL, 0ULL};

#pragma unroll
        for (int kk4 = 0; kk4 < 4; ++kk4) {
            const int k = kbase + kk4 * 4;
#pragma unroll
            for (int b = 0; b < 4; ++b) {
                float4 hv = *reinterpret_cast<const float4*>(&hc[b * HH + k]);
                unsigned long long hh;
                hh = pack_dup(hv.x);
                ffma2(a01[b], hh, w01[kk4 * 4 + 0]);
                ffma2(a23[b], hh, w23[kk4 * 4 + 0]);
                hh = pack_dup(hv.y);
                ffma2(a01[b], hh, w01[kk4 * 4 + 1]);
                ffma2(a23[b], hh, w23[kk4 * 4 + 1]);
                hh = pack_dup(hv.z);
                ffma2(a01[b], hh, w01[kk4 * 4 + 2]);
                ffma2(a23[b], hh, w23[kk4 * 4 + 2]);
                hh = pack_dup(hv.w);
                ffma2(a01[b], hh, w01[kk4 * 4 + 3]);
                ffma2(a23[b], hh, w23[kk4 * 4 + 3]);
            }
        }

        // warp pre-reduce: lane L += lane L+16 (kq pair, same cols)
#pragma unroll
        for (int b = 0; b < 4; ++b) {
            a01[b] = add2(a01[b], shfl_down16_b64(a01[b]));
            a23[b] = add2(a23[b], shfl_down16_b64(a23[b]));
        }

        // pre-reduced partials -> red[p][kq2][b][4cq..4cq+3] (lanes < 16)
        float* rp = red + p * RED16_ELEMS;
        if (is_lo) {
#pragma unroll
            for (int b = 0; b < 4; ++b) {
                ulonglong2 v;
                v.x = a01[b];
                v.y = a23[b];
                *reinterpret_cast<ulonglong2*>(
                    &rp[(kq2 * BATCH_PER_CL + b) * COLS_PER_CTA + cq * 4]) = v;
            }
        }
        __syncthreads();   // the ONLY block barrier per step

        if (is_red) {
            // 16-way reduce, 4 parallel chains
            float s0 = xw, s1 = 0.f, s2 = 0.f, s3 = 0.f;
#pragma unroll
            for (int qd = 0; qd < 4; ++qd) {
                s0 += rp[((4 * qd + 0) * BATCH_PER_CL + fb) * COLS_PER_CTA + fc];
                s1 += rp[((4 * qd + 1) * BATCH_PER_CL + fb) * COLS_PER_CTA + fc];
                s2 += rp[((4 * qd + 2) * BATCH_PER_CL + fb) * COLS_PER_CTA + fc];
                s3 += rp[((4 * qd + 3) * BATCH_PER_CL + fb) * COLS_PER_CTA + fc];
            }
            float s = (s0 + s1) + (s2 + s3);
            float r;
            asm("tanh.approx.f32 %0, %1;" : "=f"(r) : "f"(s));
            outp[(size_t)t * HH] = r;

            if (t + 1 < TT) {
                // WAIT-FREE store (causal chain; see header comment).
                float rn = __shfl_down_sync(0xFFFFFFFFu, r, 1);
                if (is_store) {
                    unsigned long long v = pack2(r, rn);
                    const uint32_t off =
                        (uint32_t)((q * BATCH_PER_CL + fb) * HH + jg) * 4u;
                    const uint32_t mboff = (uint32_t)MB_FULL(q, (int)rank);
#pragma unroll
                    for (int pp = 0; pp < CLUSTER; ++pp)
                        st_async_b64(rbase[pp] + off, v, rbase[pp] + mboff);
                }
            }
        }
        // no trailing barrier: red double-buffered; cross-step ordering
        // guaranteed by bar(t) between reduce-read(t-1) and STS(t+1).
    }

    // drain before exit
    asm volatile("barrier.cluster.arrive.aligned;\n\t"
                 "barrier.cluster.wait.aligned;" ::: "memory");
}

// ---------------------------------------------------------------------------
// Launch
// ---------------------------------------------------------------------------
extern "C" void kernel_launch(void* const* d_in, const int* in_sizes, int n_in,
                              void* d_out, int out_size) {
    const float* x  = (const float*)d_in[0];
    const float* h0 = (const float*)d_in[1];
    const float* Wx = (const float*)d_in[2];
    const float* Wh = (const float*)d_in[3];
    const float* b  = (const float*)d_in[4];
    float* out = (float*)d_out;

    (void)in_sizes; (void)n_in; (void)out_size;

    dim3 gridA(HH / BN, MM / BM);
    gemm_xwx_kernel<<<gridA, 256>>>(x, Wx, b, out);

    cudaFuncSetAttribute(rnn_cluster_kernel,
                         cudaFuncAttributeMaxDynamicSharedMemorySize,
                         RNN_SMEM_BYTES);
    rnn_cluster_kernel<<<NCTA, 512, RNN_SMEM_BYTES>>>(h0, Wh, out);
}